// round 5
// baseline (speedup 1.0000x reference)
#include <cuda_runtime.h>
#include <cuda_bf16.h>
#include <cstdint>

#define N_NODES 100000
#define N_EDGES 1200000
#define D 64
#define CAP 64                 // max in-degree capacity (Poisson(12): P(>=64) ~ 5e-26)
#define GEMM_NODES 32          // nodes per block; 100000 % 32 == 0 -> no guards
#define FPAD 68                // padded f row (even -> 8B/16B alignment holds)

typedef unsigned long long u64;

// ---- scratch (__device__ globals, allocation-free) ----
__device__ int  g_count[N_NODES];
__device__ int2 g_edge[(size_t)N_NODES * CAP];   // {src, __float_as_int(coef)}

// ---- packed f32x2 helpers (Blackwell FFMA2 path) ----
__device__ __forceinline__ u64 fma2(u64 a, u64 b, u64 c) {
    u64 d; asm("fma.rn.f32x2 %0, %1, %2, %3;" : "=l"(d) : "l"(a), "l"(b), "l"(c));
    return d;
}
__device__ __forceinline__ u64 mul2(u64 a, u64 b) {
    u64 d; asm("mul.rn.f32x2 %0, %1, %2;" : "=l"(d) : "l"(a), "l"(b));
    return d;
}
__device__ __forceinline__ u64 add2(u64 a, u64 b) {
    u64 d; asm("add.rn.f32x2 %0, %1, %2;" : "=l"(d) : "l"(a), "l"(b));
    return d;
}
__device__ __forceinline__ u64 pack2(float lo, float hi) {
    u64 d; asm("mov.b64 %0, {%1, %2};" : "=l"(d) : "f"(lo), "f"(hi));
    return d;
}
__device__ __forceinline__ float2 unpack2(u64 v) {
    float2 r; asm("mov.b64 {%0, %1}, %2;" : "=f"(r.x), "=f"(r.y) : "l"(v));
    return r;
}

// ---------------------------------------------------------------------------
// Build: single scatter pass into fixed-capacity buckets.
// ---------------------------------------------------------------------------
__global__ void __launch_bounds__(256) scatter_kernel(
    const int* __restrict__ src, const int* __restrict__ dst,
    const float* __restrict__ norm)
{
    int e = blockIdx.x * blockDim.x + threadIdx.x;
    if (e >= N_EDGES) return;
    int s = src[e], d = dst[e];
    float c = __ldg(norm + s) * __ldg(norm + d);
    int pos = atomicAdd(&g_count[d], 1);
    g_edge[(size_t)d * CAP + pos] = make_int2(s, __float_as_int(c));
}

// ---------------------------------------------------------------------------
// Fused aggregate + dual-GEMM. 128 threads (4 warps), 32 nodes per block.
// Phase B: warp-per-node; two half-warps each cover the 64-col row with
//          16B (ulonglong2) lanes, striding edges by 2 with x2 unroll.
//          All feature math in packed f32x2. shfl-combine halves.
// Phase C: out = f1@W1 + f2@W2 + b1 + b2 with f32x2 FMAs packed over
//          k-pairs (f pairs native from smem; W pairs built via mov.b64).
// ---------------------------------------------------------------------------
__global__ void __launch_bounds__(128, 8) fused_kernel(
    const float* __restrict__ x,
    const float* __restrict__ W1, const float* __restrict__ b1,
    const float* __restrict__ W2, const float* __restrict__ b2,
    float* __restrict__ out)
{
    extern __shared__ float sh[];
    float* f1s = sh;                        // 32*68
    float* f2s = f1s + GEMM_NODES * FPAD;   // 32*68

    int t = threadIdx.x;
    int node0 = blockIdx.x * GEMM_NODES;

    // ---- Phase B: aggregation (packed) ----
    int w = t >> 5, lane = t & 31;
    int half = lane >> 4;         // 0 or 1
    int le = lane & 15;           // 16B chunk within 64-col row
    const ulonglong2* xu = reinterpret_cast<const ulonglong2*>(x);

    #pragma unroll 1
    for (int j = 0; j < 8; j++) {
        int row = w * 8 + j;
        int n = node0 + row;                 // always < N_NODES (exact tiling)
        ulonglong2 vd = __ldg(xu + n * 16 + le);
        int cnt = __ldg(g_count + n);
        const int2* ep = g_edge + (size_t)n * CAP;

        u64 a1p0 = 0, a1p1 = 0, a2p0 = 0, a2p1 = 0;
        int e = half;
        for (; e + 2 < cnt; e += 4) {
            int2 ea = __ldg(ep + e);
            int2 eb = __ldg(ep + e + 2);
            u64 ca = pack2(__int_as_float(ea.y), __int_as_float(ea.y));
            u64 cb = pack2(__int_as_float(eb.y), __int_as_float(eb.y));
            ulonglong2 va = __ldg(xu + ea.x * 16 + le);
            ulonglong2 vb = __ldg(xu + eb.x * 16 + le);
            a1p0 = fma2(va.x, ca, a1p0);
            a1p1 = fma2(va.y, ca, a1p1);
            a2p0 = fma2(mul2(va.x, vd.x), ca, a2p0);
            a2p1 = fma2(mul2(va.y, vd.y), ca, a2p1);
            a1p0 = fma2(vb.x, cb, a1p0);
            a1p1 = fma2(vb.y, cb, a1p1);
            a2p0 = fma2(mul2(vb.x, vd.x), cb, a2p0);
            a2p1 = fma2(mul2(vb.y, vd.y), cb, a2p1);
        }
        if (e < cnt) {
            int2 ea = __ldg(ep + e);
            u64 ca = pack2(__int_as_float(ea.y), __int_as_float(ea.y));
            ulonglong2 va = __ldg(xu + ea.x * 16 + le);
            a1p0 = fma2(va.x, ca, a1p0);
            a1p1 = fma2(va.y, ca, a1p1);
            a2p0 = fma2(mul2(va.x, vd.x), ca, a2p0);
            a2p1 = fma2(mul2(va.y, vd.y), ca, a2p1);
        }

        // combine halves (half1 -> half0), packed adds
        a1p0 = add2(a1p0, __shfl_down_sync(0xffffffffu, a1p0, 16));
        a1p1 = add2(a1p1, __shfl_down_sync(0xffffffffu, a1p1, 16));
        a2p0 = add2(a2p0, __shfl_down_sync(0xffffffffu, a2p0, 16));
        a2p1 = add2(a2p1, __shfl_down_sync(0xffffffffu, a2p1, 16));
        if (half == 0) {
            ulonglong2 s1; s1.x = a1p0; s1.y = a1p1;
            ulonglong2 s2; s2.x = a2p0; s2.y = a2p1;
            *reinterpret_cast<ulonglong2*>(&f1s[row * FPAD + 4 * le]) = s1;
            *reinterpret_cast<ulonglong2*>(&f2s[row * FPAD + 4 * le]) = s2;
        }
    }
    __syncthreads();

    // ---- Phase C: dual GEMM, f32x2 packed over k-pairs ----
    int cg = t & 15;
    int c0 = cg * 4;
    int ns = t >> 4;              // 0..7, nodes ns*4 .. ns*4+3

    const float4* W1v = reinterpret_cast<const float4*>(W1);
    const float4* W2v = reinterpret_cast<const float4*>(W2);

    u64 acc[4][4];                // [node i][col c], lanes = even/odd-k partials
    #pragma unroll
    for (int i = 0; i < 4; i++)
        #pragma unroll
        for (int c = 0; c < 4; c++) acc[i][c] = 0ull;

    #pragma unroll 4
    for (int k = 0; k < D; k += 2) {
        float4 w1a = __ldg(W1v + k * 16 + cg);
        float4 w1b = __ldg(W1v + (k + 1) * 16 + cg);
        float4 w2a = __ldg(W2v + k * 16 + cg);
        float4 w2b = __ldg(W2v + (k + 1) * 16 + cg);
        u64 w1p[4] = { pack2(w1a.x, w1b.x), pack2(w1a.y, w1b.y),
                       pack2(w1a.z, w1b.z), pack2(w1a.w, w1b.w) };
        u64 w2p[4] = { pack2(w2a.x, w2b.x), pack2(w2a.y, w2b.y),
                       pack2(w2a.z, w2b.z), pack2(w2a.w, w2b.w) };
        #pragma unroll
        for (int i = 0; i < 4; i++) {
            u64 f1p = *reinterpret_cast<const u64*>(&f1s[(ns * 4 + i) * FPAD + k]);
            u64 f2p = *reinterpret_cast<const u64*>(&f2s[(ns * 4 + i) * FPAD + k]);
            #pragma unroll
            for (int c = 0; c < 4; c++) {
                acc[i][c] = fma2(f1p, w1p[c], acc[i][c]);
                acc[i][c] = fma2(f2p, w2p[c], acc[i][c]);
            }
        }
    }

    float4 bb1 = __ldg(reinterpret_cast<const float4*>(b1) + cg);
    float4 bb2 = __ldg(reinterpret_cast<const float4*>(b2) + cg);
    float4 bias = make_float4(bb1.x + bb2.x, bb1.y + bb2.y,
                              bb1.z + bb2.z, bb1.w + bb2.w);

    #pragma unroll
    for (int i = 0; i < 4; i++) {
        int node = node0 + ns * 4 + i;
        float2 p0 = unpack2(acc[i][0]);
        float2 p1 = unpack2(acc[i][1]);
        float2 p2 = unpack2(acc[i][2]);
        float2 p3 = unpack2(acc[i][3]);
        float4 r = make_float4(p0.x + p0.y + bias.x,
                               p1.x + p1.y + bias.y,
                               p2.x + p2.y + bias.z,
                               p3.x + p3.y + bias.w);
        *reinterpret_cast<float4*>(&out[node * D + c0]) = r;
    }
}

// ---------------------------------------------------------------------------
// Launch
// ---------------------------------------------------------------------------
extern "C" void kernel_launch(void* const* d_in, const int* in_sizes, int n_in,
                              void* d_out, int out_size)
{
    const float* x    = (const float*)d_in[0];
    const float* norm = (const float*)d_in[1];
    const int*   src  = (const int*)  d_in[2];
    const int*   dst  = (const int*)  d_in[3];
    const float* W1   = (const float*)d_in[4];
    const float* b1   = (const float*)d_in[5];
    const float* W2   = (const float*)d_in[6];
    const float* b2   = (const float*)d_in[7];
    float* out = (float*)d_out;

    void* count_ptr;
    cudaGetSymbolAddress(&count_ptr, g_count);
    cudaMemsetAsync(count_ptr, 0, sizeof(int) * N_NODES);

    int eblocks = (N_EDGES + 255) / 256;
    scatter_kernel<<<eblocks, 256>>>(src, dst, norm);

    size_t shmem = sizeof(float) * (2 * GEMM_NODES * FPAD);
    cudaFuncSetAttribute(fused_kernel,
                         cudaFuncAttributeMaxDynamicSharedMemorySize,
                         (int)shmem);
    int grid = N_NODES / GEMM_NODES;   // exact: 100000 / 32 = 3125
    fused_kernel<<<grid, 128, shmem>>>(x, W1, b1, W2, b2, out);
}

// round 6
// speedup vs baseline: 2.0876x; 2.0876x over previous
#include <cuda_runtime.h>
#include <cuda_bf16.h>
#include <cstdint>

#define N_NODES 100000
#define N_EDGES 1200000
#define D 64
#define CAP 64                 // max in-degree capacity (Poisson(12): P(>=64) ~ 5e-26)
#define GEMM_NODES 32          // nodes per block; 100000 % 32 == 0 -> no guards
#define FPAD 68                // padded f row: mult of 4 (16B aligned), bank spread

// ---- scratch (__device__ globals, allocation-free) ----
__device__ int  g_count[N_NODES];
__device__ int2 g_edge[(size_t)N_NODES * CAP];   // {src, __float_as_int(coef)}

// ---------------------------------------------------------------------------
// Build: single scatter pass into fixed-capacity buckets.
// ---------------------------------------------------------------------------
__global__ void __launch_bounds__(256) scatter_kernel(
    const int* __restrict__ src, const int* __restrict__ dst,
    const float* __restrict__ norm)
{
    int e = blockIdx.x * blockDim.x + threadIdx.x;
    if (e >= N_EDGES) return;
    int s = src[e], d = dst[e];
    float c = __ldg(norm + s) * __ldg(norm + d);
    int pos = atomicAdd(&g_count[d], 1);
    g_edge[(size_t)d * CAP + pos] = make_int2(s, __float_as_int(c));
}

// ---- one edge's contribution (scalar float4 FFMA) ----
__device__ __forceinline__ void edge_fma(
    float4 va, float c, float4 vd, float4& a1, float4& a2)
{
    a1.x = fmaf(va.x, c, a1.x); a1.y = fmaf(va.y, c, a1.y);
    a1.z = fmaf(va.z, c, a1.z); a1.w = fmaf(va.w, c, a1.w);
    a2.x = fmaf(va.x * vd.x, c, a2.x); a2.y = fmaf(va.y * vd.y, c, a2.y);
    a2.z = fmaf(va.z * vd.z, c, a2.z); a2.w = fmaf(va.w * vd.w, c, a2.w);
}

// ---------------------------------------------------------------------------
// Fused aggregate + dual-GEMM. 128 threads (4 warps), 32 nodes per block.
// Phase B: warp-per-node; half-warps stride the edge list by 2 with a
//          4/2/1 unroll ladder (up to 8 gathers in flight per warp).
// Phase C: out = f1@W1 + f2@W2 + b1 + b2; f from shared (LDS.128),
//          W via __ldg (L1-resident, warp-uniform addresses).
// ---------------------------------------------------------------------------
__global__ void __launch_bounds__(128, 8) fused_kernel(
    const float* __restrict__ x,
    const float* __restrict__ W1, const float* __restrict__ b1,
    const float* __restrict__ W2, const float* __restrict__ b2,
    float* __restrict__ out)
{
    extern __shared__ float sh[];
    float* f1s = sh;                        // 32*68
    float* f2s = f1s + GEMM_NODES * FPAD;   // 32*68

    int t = threadIdx.x;
    int node0 = blockIdx.x * GEMM_NODES;

    // ---- Phase B: aggregation ----
    int w = t >> 5, lane = t & 31;
    int half = lane >> 4;         // 0 or 1
    int le = lane & 15;           // float4 chunk within 64-col row
    const float4* x4 = reinterpret_cast<const float4*>(x);

    // Prefetch the 8 in-degrees this warp needs (off the critical path)
    int cnts[8];
    #pragma unroll
    for (int j = 0; j < 8; j++)
        cnts[j] = __ldg(g_count + node0 + w * 8 + j);

    #pragma unroll 1
    for (int j = 0; j < 8; j++) {
        int row = w * 8 + j;
        int n = node0 + row;                 // exact tiling: always valid
        float4 vd = __ldg(x4 + n * 16 + le);
        int cnt = cnts[j];
        const int2* ep = g_edge + (size_t)n * CAP;

        float4 a1 = make_float4(0.f, 0.f, 0.f, 0.f);
        float4 a2 = make_float4(0.f, 0.f, 0.f, 0.f);

        int e = half;
        // 4-edge batches per half-warp (8 gathers in flight per warp)
        for (; e + 6 < cnt; e += 8) {
            int2 r0 = __ldg(ep + e);
            int2 r1 = __ldg(ep + e + 2);
            int2 r2 = __ldg(ep + e + 4);
            int2 r3 = __ldg(ep + e + 6);
            float4 v0 = __ldg(x4 + r0.x * 16 + le);
            float4 v1 = __ldg(x4 + r1.x * 16 + le);
            float4 v2 = __ldg(x4 + r2.x * 16 + le);
            float4 v3 = __ldg(x4 + r3.x * 16 + le);
            edge_fma(v0, __int_as_float(r0.y), vd, a1, a2);
            edge_fma(v1, __int_as_float(r1.y), vd, a1, a2);
            edge_fma(v2, __int_as_float(r2.y), vd, a1, a2);
            edge_fma(v3, __int_as_float(r3.y), vd, a1, a2);
        }
        // 2-edge batch
        for (; e + 2 < cnt; e += 4) {
            int2 r0 = __ldg(ep + e);
            int2 r1 = __ldg(ep + e + 2);
            float4 v0 = __ldg(x4 + r0.x * 16 + le);
            float4 v1 = __ldg(x4 + r1.x * 16 + le);
            edge_fma(v0, __int_as_float(r0.y), vd, a1, a2);
            edge_fma(v1, __int_as_float(r1.y), vd, a1, a2);
        }
        // final single
        if (e < cnt) {
            int2 r0 = __ldg(ep + e);
            float4 v0 = __ldg(x4 + r0.x * 16 + le);
            edge_fma(v0, __int_as_float(r0.y), vd, a1, a2);
        }

        // combine halves (half1 -> half0)
        a1.x += __shfl_down_sync(0xffffffffu, a1.x, 16);
        a1.y += __shfl_down_sync(0xffffffffu, a1.y, 16);
        a1.z += __shfl_down_sync(0xffffffffu, a1.z, 16);
        a1.w += __shfl_down_sync(0xffffffffu, a1.w, 16);
        a2.x += __shfl_down_sync(0xffffffffu, a2.x, 16);
        a2.y += __shfl_down_sync(0xffffffffu, a2.y, 16);
        a2.z += __shfl_down_sync(0xffffffffu, a2.z, 16);
        a2.w += __shfl_down_sync(0xffffffffu, a2.w, 16);
        if (half == 0) {
            *reinterpret_cast<float4*>(&f1s[row * FPAD + 4 * le]) = a1;
            *reinterpret_cast<float4*>(&f2s[row * FPAD + 4 * le]) = a2;
        }
    }
    __syncthreads();

    // ---- Phase C: dual GEMM, k blocked by 4, W from L1 via __ldg ----
    int cg = t & 15;
    int c0 = cg * 4;
    int ns = t >> 4;              // 0..7, each owns nodes ns*4..ns*4+3

    const float4* W1v = reinterpret_cast<const float4*>(W1);
    const float4* W2v = reinterpret_cast<const float4*>(W2);

    float4 acc[4];
    #pragma unroll
    for (int i = 0; i < 4; i++) acc[i] = make_float4(0.f, 0.f, 0.f, 0.f);

    #pragma unroll 4
    for (int k4 = 0; k4 < D; k4 += 4) {
        float4 fa[4], fb[4];
        #pragma unroll
        for (int i = 0; i < 4; i++) {
            fa[i] = *reinterpret_cast<const float4*>(&f1s[(ns * 4 + i) * FPAD + k4]);
            fb[i] = *reinterpret_cast<const float4*>(&f2s[(ns * 4 + i) * FPAD + k4]);
        }
        #pragma unroll
        for (int kk = 0; kk < 4; kk++) {
            float4 w1 = __ldg(W1v + (k4 + kk) * 16 + cg);
            float4 w2 = __ldg(W2v + (k4 + kk) * 16 + cg);
            #pragma unroll
            for (int i = 0; i < 4; i++) {
                float a1 = (&fa[i].x)[kk];
                float a2 = (&fb[i].x)[kk];
                acc[i].x = fmaf(a1, w1.x, fmaf(a2, w2.x, acc[i].x));
                acc[i].y = fmaf(a1, w1.y, fmaf(a2, w2.y, acc[i].y));
                acc[i].z = fmaf(a1, w1.z, fmaf(a2, w2.z, acc[i].z));
                acc[i].w = fmaf(a1, w1.w, fmaf(a2, w2.w, acc[i].w));
            }
        }
    }

    float4 bb1 = __ldg(reinterpret_cast<const float4*>(b1) + cg);
    float4 bb2 = __ldg(reinterpret_cast<const float4*>(b2) + cg);
    float4 bias = make_float4(bb1.x + bb2.x, bb1.y + bb2.y,
                              bb1.z + bb2.z, bb1.w + bb2.w);

    #pragma unroll
    for (int i = 0; i < 4; i++) {
        int node = node0 + ns * 4 + i;
        float4 r = make_float4(acc[i].x + bias.x, acc[i].y + bias.y,
                               acc[i].z + bias.z, acc[i].w + bias.w);
        *reinterpret_cast<float4*>(&out[node * D + c0]) = r;
    }
}

// ---------------------------------------------------------------------------
// Launch
// ---------------------------------------------------------------------------
extern "C" void kernel_launch(void* const* d_in, const int* in_sizes, int n_in,
                              void* d_out, int out_size)
{
    const float* x    = (const float*)d_in[0];
    const float* norm = (const float*)d_in[1];
    const int*   src  = (const int*)  d_in[2];
    const int*   dst  = (const int*)  d_in[3];
    const float* W1   = (const float*)d_in[4];
    const float* b1   = (const float*)d_in[5];
    const float* W2   = (const float*)d_in[6];
    const float* b2   = (const float*)d_in[7];
    float* out = (float*)d_out;

    void* count_ptr;
    cudaGetSymbolAddress(&count_ptr, g_count);
    cudaMemsetAsync(count_ptr, 0, sizeof(int) * N_NODES);

    int eblocks = (N_EDGES + 255) / 256;
    scatter_kernel<<<eblocks, 256>>>(src, dst, norm);

    size_t shmem = sizeof(float) * (2 * GEMM_NODES * FPAD);
    cudaFuncSetAttribute(fused_kernel,
                         cudaFuncAttributeMaxDynamicSharedMemorySize,
                         (int)shmem);
    int grid = N_NODES / GEMM_NODES;   // exact: 100000 / 32 = 3125
    fused_kernel<<<grid, 128, shmem>>>(x, W1, b1, W2, b2, out);
}

// round 7
// speedup vs baseline: 2.2551x; 1.0802x over previous
#include <cuda_runtime.h>
#include <cuda_bf16.h>
#include <cstdint>

#define N_NODES 100000
#define N_EDGES 1200000
#define D 64
#define CAP 64                 // max in-degree capacity (Poisson(12): P(>=64) ~ 5e-26)
#define GEMM_NODES 32          // nodes per block; 100000 % 32 == 0 -> no guards
#define FPAD 68                // padded f row: mult of 4 (16B aligned), bank spread

// ---- scratch (__device__ globals, allocation-free) ----
__device__ int  g_count[N_NODES];
__device__ int2 g_edge[(size_t)N_NODES * CAP];   // {src, __float_as_int(coef)}

// ---------------------------------------------------------------------------
// Build: single scatter pass into fixed-capacity buckets.
// ---------------------------------------------------------------------------
__global__ void __launch_bounds__(256) scatter_kernel(
    const int* __restrict__ src, const int* __restrict__ dst,
    const float* __restrict__ norm)
{
    int e = blockIdx.x * blockDim.x + threadIdx.x;
    if (e >= N_EDGES) return;
    int s = src[e], d = dst[e];
    float c = __ldg(norm + s) * __ldg(norm + d);
    int pos = atomicAdd(&g_count[d], 1);
    g_edge[(size_t)d * CAP + pos] = make_int2(s, __float_as_int(c));
}

// ---- one edge's f1 contribution (4 scalar FFMAs) ----
__device__ __forceinline__ void edge_fma(float4 va, float c, float4& a1)
{
    a1.x = fmaf(va.x, c, a1.x); a1.y = fmaf(va.y, c, a1.y);
    a1.z = fmaf(va.z, c, a1.z); a1.w = fmaf(va.w, c, a1.w);
}

// ---------------------------------------------------------------------------
// Fused aggregate + dual-GEMM. 128 threads (4 warps), 32 nodes per block.
// KEY IDENTITY: f2[n] = x[n] (elementwise*) f1[n], so the edge loop only
// accumulates f1 = sum coef * x[src]; f2 is one Hadamard product per node.
// Phase B: warp-per-node; half-warps stride the edge list by 2 with a
//          4/2/1 unroll ladder (up to 8 gathers in flight per warp).
// Phase C: out = f1@W1 + f2@W2 + b1 + b2; f from shared (LDS.128),
//          W via __ldg (L1-resident, warp-uniform addresses).
// ---------------------------------------------------------------------------
__global__ void __launch_bounds__(128, 8) fused_kernel(
    const float* __restrict__ x,
    const float* __restrict__ W1, const float* __restrict__ b1,
    const float* __restrict__ W2, const float* __restrict__ b2,
    float* __restrict__ out)
{
    extern __shared__ float sh[];
    float* f1s = sh;                        // 32*68
    float* f2s = f1s + GEMM_NODES * FPAD;   // 32*68

    int t = threadIdx.x;
    int node0 = blockIdx.x * GEMM_NODES;

    // ---- Phase B: aggregation (f1 only) ----
    int w = t >> 5, lane = t & 31;
    int half = lane >> 4;         // 0 or 1
    int le = lane & 15;           // float4 chunk within 64-col row
    const float4* x4 = reinterpret_cast<const float4*>(x);

    // Prefetch the 8 in-degrees this warp needs (off the critical path)
    int cnts[8];
    #pragma unroll
    for (int j = 0; j < 8; j++)
        cnts[j] = __ldg(g_count + node0 + w * 8 + j);

    #pragma unroll 1
    for (int j = 0; j < 8; j++) {
        int row = w * 8 + j;
        int n = node0 + row;                 // exact tiling: always valid
        int cnt = cnts[j];
        const int2* ep = g_edge + (size_t)n * CAP;

        float4 a1 = make_float4(0.f, 0.f, 0.f, 0.f);

        int e = half;
        // 4-edge batches per half-warp (8 gathers in flight per warp)
        for (; e + 6 < cnt; e += 8) {
            int2 r0 = __ldg(ep + e);
            int2 r1 = __ldg(ep + e + 2);
            int2 r2 = __ldg(ep + e + 4);
            int2 r3 = __ldg(ep + e + 6);
            float4 v0 = __ldg(x4 + r0.x * 16 + le);
            float4 v1 = __ldg(x4 + r1.x * 16 + le);
            float4 v2 = __ldg(x4 + r2.x * 16 + le);
            float4 v3 = __ldg(x4 + r3.x * 16 + le);
            edge_fma(v0, __int_as_float(r0.y), a1);
            edge_fma(v1, __int_as_float(r1.y), a1);
            edge_fma(v2, __int_as_float(r2.y), a1);
            edge_fma(v3, __int_as_float(r3.y), a1);
        }
        // 2-edge batch
        for (; e + 2 < cnt; e += 4) {
            int2 r0 = __ldg(ep + e);
            int2 r1 = __ldg(ep + e + 2);
            float4 v0 = __ldg(x4 + r0.x * 16 + le);
            float4 v1 = __ldg(x4 + r1.x * 16 + le);
            edge_fma(v0, __int_as_float(r0.y), a1);
            edge_fma(v1, __int_as_float(r1.y), a1);
        }
        // final single
        if (e < cnt) {
            int2 r0 = __ldg(ep + e);
            float4 v0 = __ldg(x4 + r0.x * 16 + le);
            edge_fma(v0, __int_as_float(r0.y), a1);
        }

        // combine halves (half1 -> half0)
        a1.x += __shfl_down_sync(0xffffffffu, a1.x, 16);
        a1.y += __shfl_down_sync(0xffffffffu, a1.y, 16);
        a1.z += __shfl_down_sync(0xffffffffu, a1.z, 16);
        a1.w += __shfl_down_sync(0xffffffffu, a1.w, 16);
        if (half == 0) {
            // f2 = x[n] (elementwise) f1  — once per node, not per edge
            float4 vd = __ldg(x4 + n * 16 + le);
            float4 a2 = make_float4(a1.x * vd.x, a1.y * vd.y,
                                    a1.z * vd.z, a1.w * vd.w);
            *reinterpret_cast<float4*>(&f1s[row * FPAD + 4 * le]) = a1;
            *reinterpret_cast<float4*>(&f2s[row * FPAD + 4 * le]) = a2;
        }
    }
    __syncthreads();

    // ---- Phase C: dual GEMM, k blocked by 4, W from L1 via __ldg ----
    int cg = t & 15;
    int c0 = cg * 4;
    int ns = t >> 4;              // 0..7, each owns nodes ns*4..ns*4+3

    const float4* W1v = reinterpret_cast<const float4*>(W1);
    const float4* W2v = reinterpret_cast<const float4*>(W2);

    float4 acc[4];
    #pragma unroll
    for (int i = 0; i < 4; i++) acc[i] = make_float4(0.f, 0.f, 0.f, 0.f);

    #pragma unroll 4
    for (int k4 = 0; k4 < D; k4 += 4) {
        float4 fa[4], fb[4];
        #pragma unroll
        for (int i = 0; i < 4; i++) {
            fa[i] = *reinterpret_cast<const float4*>(&f1s[(ns * 4 + i) * FPAD + k4]);
            fb[i] = *reinterpret_cast<const float4*>(&f2s[(ns * 4 + i) * FPAD + k4]);
        }
        #pragma unroll
        for (int kk = 0; kk < 4; kk++) {
            float4 w1 = __ldg(W1v + (k4 + kk) * 16 + cg);
            float4 w2 = __ldg(W2v + (k4 + kk) * 16 + cg);
            #pragma unroll
            for (int i = 0; i < 4; i++) {
                float a1 = (&fa[i].x)[kk];
                float a2 = (&fb[i].x)[kk];
                acc[i].x = fmaf(a1, w1.x, fmaf(a2, w2.x, acc[i].x));
                acc[i].y = fmaf(a1, w1.y, fmaf(a2, w2.y, acc[i].y));
                acc[i].z = fmaf(a1, w1.z, fmaf(a2, w2.z, acc[i].z));
                acc[i].w = fmaf(a1, w1.w, fmaf(a2, w2.w, acc[i].w));
            }
        }
    }

    float4 bb1 = __ldg(reinterpret_cast<const float4*>(b1) + cg);
    float4 bb2 = __ldg(reinterpret_cast<const float4*>(b2) + cg);
    float4 bias = make_float4(bb1.x + bb2.x, bb1.y + bb2.y,
                              bb1.z + bb2.z, bb1.w + bb2.w);

    #pragma unroll
    for (int i = 0; i < 4; i++) {
        int node = node0 + ns * 4 + i;
        float4 r = make_float4(acc[i].x + bias.x, acc[i].y + bias.y,
                               acc[i].z + bias.z, acc[i].w + bias.w);
        *reinterpret_cast<float4*>(&out[node * D + c0]) = r;
    }
}

// ---------------------------------------------------------------------------
// Launch
// ---------------------------------------------------------------------------
extern "C" void kernel_launch(void* const* d_in, const int* in_sizes, int n_in,
                              void* d_out, int out_size)
{
    const float* x    = (const float*)d_in[0];
    const float* norm = (const float*)d_in[1];
    const int*   src  = (const int*)  d_in[2];
    const int*   dst  = (const int*)  d_in[3];
    const float* W1   = (const float*)d_in[4];
    const float* b1   = (const float*)d_in[5];
    const float* W2   = (const float*)d_in[6];
    const float* b2   = (const float*)d_in[7];
    float* out = (float*)d_out;

    void* count_ptr;
    cudaGetSymbolAddress(&count_ptr, g_count);
    cudaMemsetAsync(count_ptr, 0, sizeof(int) * N_NODES);

    int eblocks = (N_EDGES + 255) / 256;
    scatter_kernel<<<eblocks, 256>>>(src, dst, norm);

    size_t shmem = sizeof(float) * (2 * GEMM_NODES * FPAD);
    cudaFuncSetAttribute(fused_kernel,
                         cudaFuncAttributeMaxDynamicSharedMemorySize,
                         (int)shmem);
    int grid = N_NODES / GEMM_NODES;   // exact: 100000 / 32 = 3125
    fused_kernel<<<grid, 128, shmem>>>(x, W1, b1, W2, b2, out);
}

// round 8
// speedup vs baseline: 2.6510x; 1.1756x over previous
#include <cuda_runtime.h>
#include <cuda_bf16.h>
#include <cstdint>

#define N_NODES 100000
#define N_EDGES 1200000
#define D 64
#define CAP 64                 // max in-degree capacity (Poisson(12): P(>=64) ~ 5e-26)
#define GEMM_NODES 32          // nodes per block; exact tiling
#define FPAD 68                // padded f row: bank = lane%32 for frag loads

// ---- scratch (__device__ globals, allocation-free) ----
__device__ int    g_count[N_NODES];
__device__ int2   g_edge[(size_t)N_NODES * CAP];   // {src, __float_as_int(coef)}
__device__ float2 g_Wh[2][8][8][32];   // [part][kstep][ntile][lane] = (b0,b1) hi
__device__ float2 g_Wl[2][8][8][32];   // lo residual fragments

// ---- tf32 helpers ----
__device__ __forceinline__ uint32_t tf32_of(float a) {
    uint32_t r; asm("cvt.rna.tf32.f32 %0, %1;" : "=r"(r) : "f"(a));
    return r;
}
__device__ __forceinline__ void mma_tf32(float4& d,
    uint32_t a0, uint32_t a1, uint32_t a2, uint32_t a3,
    uint32_t b0, uint32_t b1)
{
    asm("mma.sync.aligned.m16n8k8.row.col.f32.tf32.tf32.f32 "
        "{%0,%1,%2,%3}, {%4,%5,%6,%7}, {%8,%9}, {%0,%1,%2,%3};"
        : "+f"(d.x), "+f"(d.y), "+f"(d.z), "+f"(d.w)
        : "r"(a0), "r"(a1), "r"(a2), "r"(a3), "r"(b0), "r"(b1));
}

// ---------------------------------------------------------------------------
// Build: scatter into fixed-capacity buckets.
// ---------------------------------------------------------------------------
__global__ void __launch_bounds__(256) scatter_kernel(
    const int* __restrict__ src, const int* __restrict__ dst,
    const float* __restrict__ norm)
{
    int e = blockIdx.x * blockDim.x + threadIdx.x;
    if (e >= N_EDGES) return;
    int s = src[e], d = dst[e];
    float c = __ldg(norm + s) * __ldg(norm + d);
    int pos = atomicAdd(&g_count[d], 1);
    g_edge[(size_t)d * CAP + pos] = make_int2(s, __float_as_int(c));
}

// ---------------------------------------------------------------------------
// W fragment precompute: hi/lo tf32 split in m16n8k8 B-fragment layout.
// B (col-major k8 x n8): b0 = W[k=tig][n=g], b1 = W[k=tig+4][n=g].
// ---------------------------------------------------------------------------
__global__ void __launch_bounds__(256) wfrag_kernel(
    const float* __restrict__ W1, const float* __restrict__ W2)
{
    int idx = blockIdx.x * blockDim.x + threadIdx.x;   // 0..4095
    if (idx >= 4096) return;
    int lane  = idx & 31;
    int ntile = (idx >> 5) & 7;
    int kstep = (idx >> 8) & 7;
    int part  = idx >> 11;
    const float* W = part ? W2 : W1;
    int g = lane >> 2, tig = lane & 3;
    int n  = ntile * 8 + g;
    int k0 = kstep * 8 + tig;
    float b0 = __ldg(W + k0 * D + n);
    float b1 = __ldg(W + (k0 + 4) * D + n);
    uint32_t h0 = tf32_of(b0), h1 = tf32_of(b1);
    float r0 = b0 - __uint_as_float(h0);
    float r1 = b1 - __uint_as_float(h1);
    g_Wh[part][kstep][ntile][lane] =
        make_float2(__uint_as_float(h0), __uint_as_float(h1));
    g_Wl[part][kstep][ntile][lane] =
        make_float2(__uint_as_float(tf32_of(r0)), __uint_as_float(tf32_of(r1)));
}

// ---- one edge's f1 contribution ----
__device__ __forceinline__ void edge_fma(float4 va, float c, float4& a1)
{
    a1.x = fmaf(va.x, c, a1.x); a1.y = fmaf(va.y, c, a1.y);
    a1.z = fmaf(va.z, c, a1.z); a1.w = fmaf(va.w, c, a1.w);
}

// ---------------------------------------------------------------------------
// Fused aggregate + dual-GEMM. 128 threads, 32 nodes per block.
// Phase B: f1 = sum coef*x[src] (f2 = x[n] .* f1 identity); half-warp
//          striding, 4/2/1 unroll ladder.
// Phase C: 3xTF32 m16n8k8 warp MMA. Warp w owns cols [w*16, w*16+16).
//          A frags from row-major smem (conflict-free), hi/lo split in regs.
// ---------------------------------------------------------------------------
__global__ void __launch_bounds__(128, 8) fused_kernel(
    const float* __restrict__ x,
    const float* __restrict__ b1v, const float* __restrict__ b2v,
    float* __restrict__ out)
{
    extern __shared__ float sh[];
    float* f1s = sh;                        // 32*68
    float* f2s = f1s + GEMM_NODES * FPAD;   // 32*68

    int t = threadIdx.x;
    int node0 = blockIdx.x * GEMM_NODES;
    int w = t >> 5, lane = t & 31;

    // ---- Phase B ----
    int half = lane >> 4;
    int le = lane & 15;
    const float4* x4 = reinterpret_cast<const float4*>(x);

    int cnts[8];
    #pragma unroll
    for (int j = 0; j < 8; j++)
        cnts[j] = __ldg(g_count + node0 + w * 8 + j);

    #pragma unroll 1
    for (int j = 0; j < 8; j++) {
        int row = w * 8 + j;
        int n = node0 + row;
        int cnt = cnts[j];
        const int2* ep = g_edge + (size_t)n * CAP;

        float4 a1 = make_float4(0.f, 0.f, 0.f, 0.f);
        int e = half;
        for (; e + 6 < cnt; e += 8) {
            int2 r0 = __ldg(ep + e);
            int2 r1 = __ldg(ep + e + 2);
            int2 r2 = __ldg(ep + e + 4);
            int2 r3 = __ldg(ep + e + 6);
            float4 v0 = __ldg(x4 + r0.x * 16 + le);
            float4 v1 = __ldg(x4 + r1.x * 16 + le);
            float4 v2 = __ldg(x4 + r2.x * 16 + le);
            float4 v3 = __ldg(x4 + r3.x * 16 + le);
            edge_fma(v0, __int_as_float(r0.y), a1);
            edge_fma(v1, __int_as_float(r1.y), a1);
            edge_fma(v2, __int_as_float(r2.y), a1);
            edge_fma(v3, __int_as_float(r3.y), a1);
        }
        for (; e + 2 < cnt; e += 4) {
            int2 r0 = __ldg(ep + e);
            int2 r1 = __ldg(ep + e + 2);
            float4 v0 = __ldg(x4 + r0.x * 16 + le);
            float4 v1 = __ldg(x4 + r1.x * 16 + le);
            edge_fma(v0, __int_as_float(r0.y), a1);
            edge_fma(v1, __int_as_float(r1.y), a1);
        }
        if (e < cnt) {
            int2 r0 = __ldg(ep + e);
            float4 v0 = __ldg(x4 + r0.x * 16 + le);
            edge_fma(v0, __int_as_float(r0.y), a1);
        }

        a1.x += __shfl_down_sync(0xffffffffu, a1.x, 16);
        a1.y += __shfl_down_sync(0xffffffffu, a1.y, 16);
        a1.z += __shfl_down_sync(0xffffffffu, a1.z, 16);
        a1.w += __shfl_down_sync(0xffffffffu, a1.w, 16);
        if (half == 0) {
            float4 vd = __ldg(x4 + n * 16 + le);
            float4 a2 = make_float4(a1.x * vd.x, a1.y * vd.y,
                                    a1.z * vd.z, a1.w * vd.w);
            *reinterpret_cast<float4*>(&f1s[row * FPAD + 4 * le]) = a1;
            *reinterpret_cast<float4*>(&f2s[row * FPAD + 4 * le]) = a2;
        }
    }
    __syncthreads();

    // ---- Phase C: 3xTF32 warp MMA ----
    int g = lane >> 2, tig = lane & 3;

    float4 acc[2][2];   // [mtile][ntile]
    #pragma unroll
    for (int mt = 0; mt < 2; mt++)
        #pragma unroll
        for (int nt = 0; nt < 2; nt++)
            acc[mt][nt] = make_float4(0.f, 0.f, 0.f, 0.f);

    #pragma unroll
    for (int part = 0; part < 2; part++) {
        const float* fs = part ? f2s : f1s;
        #pragma unroll 2
        for (int ks = 0; ks < 8; ks++) {
            uint32_t bh[2][2], bl[2][2];
            #pragma unroll
            for (int nt = 0; nt < 2; nt++) {
                float2 h = __ldg(&g_Wh[part][ks][w * 2 + nt][lane]);
                float2 l = __ldg(&g_Wl[part][ks][w * 2 + nt][lane]);
                bh[nt][0] = __float_as_uint(h.x);
                bh[nt][1] = __float_as_uint(h.y);
                bl[nt][0] = __float_as_uint(l.x);
                bl[nt][1] = __float_as_uint(l.y);
            }
            #pragma unroll
            for (int mt = 0; mt < 2; mt++) {
                int r0 = mt * 16 + g;
                int c0 = ks * 8 + tig;
                // A frag: a0=(g,c) a1=(g+8,c) a2=(g,c+4) a3=(g+8,c+4)
                float a0f = fs[r0 * FPAD + c0];
                float a1f = fs[(r0 + 8) * FPAD + c0];
                float a2f = fs[r0 * FPAD + c0 + 4];
                float a3f = fs[(r0 + 8) * FPAD + c0 + 4];
                uint32_t ah0 = tf32_of(a0f), ah1 = tf32_of(a1f);
                uint32_t ah2 = tf32_of(a2f), ah3 = tf32_of(a3f);
                uint32_t al0 = tf32_of(a0f - __uint_as_float(ah0));
                uint32_t al1 = tf32_of(a1f - __uint_as_float(ah1));
                uint32_t al2 = tf32_of(a2f - __uint_as_float(ah2));
                uint32_t al3 = tf32_of(a3f - __uint_as_float(ah3));
                #pragma unroll
                for (int nt = 0; nt < 2; nt++) {
                    mma_tf32(acc[mt][nt], ah0, ah1, ah2, ah3, bh[nt][0], bh[nt][1]);
                    mma_tf32(acc[mt][nt], ah0, ah1, ah2, ah3, bl[nt][0], bl[nt][1]);
                    mma_tf32(acc[mt][nt], al0, al1, al2, al3, bh[nt][0], bh[nt][1]);
                }
            }
        }
    }

    // ---- epilogue: bias + store (C frag: c0=(g,2tig) c1=(g,2tig+1)
    //      c2=(g+8,2tig) c3=(g+8,2tig+1)) ----
    #pragma unroll
    for (int nt = 0; nt < 2; nt++) {
        int colb = w * 16 + nt * 8 + 2 * tig;
        float bx = __ldg(b1v + colb)     + __ldg(b2v + colb);
        float by = __ldg(b1v + colb + 1) + __ldg(b2v + colb + 1);
        #pragma unroll
        for (int mt = 0; mt < 2; mt++) {
            int row0 = node0 + mt * 16 + g;
            float2 lo = make_float2(acc[mt][nt].x + bx, acc[mt][nt].y + by);
            float2 hi = make_float2(acc[mt][nt].z + bx, acc[mt][nt].w + by);
            *reinterpret_cast<float2*>(&out[row0 * D + colb]) = lo;
            *reinterpret_cast<float2*>(&out[(row0 + 8) * D + colb]) = hi;
        }
    }
}

// ---------------------------------------------------------------------------
// Launch
// ---------------------------------------------------------------------------
extern "C" void kernel_launch(void* const* d_in, const int* in_sizes, int n_in,
                              void* d_out, int out_size)
{
    const float* x    = (const float*)d_in[0];
    const float* norm = (const float*)d_in[1];
    const int*   src  = (const int*)  d_in[2];
    const int*   dst  = (const int*)  d_in[3];
    const float* W1   = (const float*)d_in[4];
    const float* b1   = (const float*)d_in[5];
    const float* W2   = (const float*)d_in[6];
    const float* b2   = (const float*)d_in[7];
    float* out = (float*)d_out;

    void* count_ptr;
    cudaGetSymbolAddress(&count_ptr, g_count);
    cudaMemsetAsync(count_ptr, 0, sizeof(int) * N_NODES);

    int eblocks = (N_EDGES + 255) / 256;
    scatter_kernel<<<eblocks, 256>>>(src, dst, norm);
    wfrag_kernel<<<16, 256>>>(W1, W2);

    size_t shmem = sizeof(float) * (2 * GEMM_NODES * FPAD);
    cudaFuncSetAttribute(fused_kernel,
                         cudaFuncAttributeMaxDynamicSharedMemorySize,
                         (int)shmem);
    int grid = N_NODES / GEMM_NODES;   // 3125
    fused_kernel<<<grid, 128, shmem>>>(x, b1, b2, out);
}